// round 3
// baseline (speedup 1.0000x reference)
#include <cuda_runtime.h>

// NBVLoss: weighted BCE reduction over 16384x4096 fp32 tensors -> scalar.
// HBM-bound streaming reduction (536 MB read). Single fused kernel:
// unrolled grid-stride stream (4x LDG.128 in flight) + last-block reduce.

#define NBLK 1184   // 148 SMs * 8 resident blocks (one full wave)
#define NTHR 256
#define NWARP (NTHR / 32)

__device__ float g_partials[NBLK];
__device__ unsigned int g_ticket = 0;   // reset to 0 by last block each run

// Fold ln(2) into weights so the log stays a single MUFU.LG2:
// contrib = -w * max(ln(x), -100) = (-w*ln2) * max(log2(x), -100/ln2)
#define LN2f 0.693147180559945309f
#define W1P  (-1.6f * LN2f)          // target == 1
#define W0P  (-0.4f * LN2f)          // target == 0
#define CLAMP2 (-100.0f / LN2f)

__device__ __forceinline__ float bce_term(float p, float t) {
    bool one = (t != 0.0f);
    float x = one ? p : (1.0f - p);
    float w = one ? W1P : W0P;
    return w * fmaxf(__log2f(x), CLAMP2);
}

__device__ __forceinline__ float bce4(float4 p, float4 t) {
    return bce_term(p.x, t.x) + bce_term(p.y, t.y) +
           bce_term(p.z, t.z) + bce_term(p.w, t.w);
}

__device__ __forceinline__ float warp_sum(float v) {
#pragma unroll
    for (int o = 16; o > 0; o >>= 1)
        v += __shfl_down_sync(0xFFFFFFFFu, v, o);
    return v;
}

__global__ __launch_bounds__(NTHR)
void bce_fused_kernel(const float4* __restrict__ pred4,
                      const float4* __restrict__ targ4,
                      const float* __restrict__ pred,
                      const float* __restrict__ targ,
                      int n4, int n,
                      float* __restrict__ out) {
    const int stride = gridDim.x * blockDim.x;
    int i = blockIdx.x * blockDim.x + threadIdx.x;

    float acc0 = 0.0f, acc1 = 0.0f;

    // Unrolled-by-2: 4 independent 16B streaming loads in flight per iter.
    for (; i < n4 - stride; i += 2 * stride) {
        float4 p0 = __ldcs(&pred4[i]);
        float4 t0 = __ldcs(&targ4[i]);
        float4 p1 = __ldcs(&pred4[i + stride]);
        float4 t1 = __ldcs(&targ4[i + stride]);
        acc0 += bce4(p0, t0);
        acc1 += bce4(p1, t1);
    }
    if (i < n4) {
        float4 p0 = __ldcs(&pred4[i]);
        float4 t0 = __ldcs(&targ4[i]);
        acc0 += bce4(p0, t0);
    }

    // scalar tail (unused for this shape, kept for safety)
    for (int j = 4 * n4 + blockIdx.x * blockDim.x + threadIdx.x; j < n; j += stride)
        acc1 += bce_term(pred[j], targ[j]);

    float acc = acc0 + acc1;

    // ---- block reduction (warp shuffle + one smem pass) ----
    __shared__ float s_warp[NWARP];
    const int lane = threadIdx.x & 31;
    const int wid  = threadIdx.x >> 5;

    acc = warp_sum(acc);
    if (lane == 0) s_warp[wid] = acc;
    __syncthreads();

    if (wid == 0) {
        float v = (lane < NWARP) ? s_warp[lane] : 0.0f;
        v = warp_sum(v);
        if (lane == 0) g_partials[blockIdx.x] = v;
    }

    // ---- last-block final reduce (deterministic: fixed-order read) ----
    __shared__ bool s_last;
    if (threadIdx.x == 0) {
        __threadfence();  // make g_partials[blockIdx.x] globally visible
        unsigned int t = atomicAdd(&g_ticket, 1u);
        s_last = (t == (unsigned int)(gridDim.x - 1));
    }
    __syncthreads();

    if (s_last) {
        float v = 0.0f;
        for (int k = threadIdx.x; k < NBLK; k += NTHR)
            v += g_partials[k];
        v = warp_sum(v);
        if (lane == 0) s_warp[wid] = v;
        __syncthreads();
        if (wid == 0) {
            float r = (lane < NWARP) ? s_warp[lane] : 0.0f;
            r = warp_sum(r);
            if (lane == 0) {
                out[0] = r;
                g_ticket = 0;   // reset for next (graph-replayed) run
            }
        }
    }
}

extern "C" void kernel_launch(void* const* d_in, const int* in_sizes, int n_in,
                              void* d_out, int out_size) {
    const float* pred = (const float*)d_in[0];
    const float* targ = (const float*)d_in[1];
    const int n = in_sizes[0];
    const int n4 = n >> 2;

    bce_fused_kernel<<<NBLK, NTHR>>>(
        (const float4*)pred, (const float4*)targ, pred, targ, n4, n,
        (float*)d_out);
}

// round 5
// speedup vs baseline: 1.0090x; 1.0090x over previous
#include <cuda_runtime.h>

// NBVLoss: weighted BCE reduction over 16384x4096 fp32 tensors -> scalar.
// HBM-bound streaming reduction (536 MB read). Block-contiguous 16KB tiles
// for DRAM row-buffer locality + fused last-block final reduce.

#define NBLK 592    // 148 SMs * 4 resident blocks
#define NTHR 256
#define NWARP (NTHR / 32)
#define UNROLL 4    // 4 x 4KB chunks = 16KB contiguous per block-tile per stream
#define TILE_F4 (NTHR * UNROLL)   // 1024 float4 per tile

__device__ float g_partials[NBLK];
__device__ unsigned int g_ticket = 0;   // reset to 0 by last block each run

// Fold ln(2) into weights so the log stays a single MUFU.LG2:
// contrib = -w * max(ln(x), -100) = (-w*ln2) * max(log2(x), -100/ln2)
#define LN2f 0.693147180559945309f
#define W1P  (-1.6f * LN2f)          // target == 1
#define W0P  (-0.4f * LN2f)          // target == 0
#define CLAMP2 (-100.0f / LN2f)

__device__ __forceinline__ float bce_term(float p, float t) {
    bool one = (t != 0.0f);
    float x = one ? p : (1.0f - p);
    float w = one ? W1P : W0P;
    return w * fmaxf(__log2f(x), CLAMP2);
}

__device__ __forceinline__ float bce4(float4 p, float4 t) {
    return bce_term(p.x, t.x) + bce_term(p.y, t.y) +
           bce_term(p.z, t.z) + bce_term(p.w, t.w);
}

__device__ __forceinline__ float warp_sum(float v) {
#pragma unroll
    for (int o = 16; o > 0; o >>= 1)
        v += __shfl_down_sync(0xFFFFFFFFu, v, o);
    return v;
}

__global__ __launch_bounds__(NTHR, 4)
void bce_fused_kernel(const float4* __restrict__ pred4,
                      const float4* __restrict__ targ4,
                      const float* __restrict__ pred,
                      const float* __restrict__ targ,
                      int n4, int n,
                      float* __restrict__ out) {
    const int ntiles = n4 / TILE_F4;
    float acc0 = 0.0f, acc1 = 0.0f;

    // Grid-stride over 16KB-contiguous block tiles.
    for (int t = blockIdx.x; t < ntiles; t += gridDim.x) {
        const float4* pb = pred4 + t * TILE_F4 + threadIdx.x;
        const float4* tb = targ4 + t * TILE_F4 + threadIdx.x;
        float4 P[UNROLL], T[UNROLL];
#pragma unroll
        for (int u = 0; u < UNROLL; u++) P[u] = __ldcs(pb + u * NTHR);
#pragma unroll
        for (int u = 0; u < UNROLL; u++) T[u] = __ldcs(tb + u * NTHR);
#pragma unroll
        for (int u = 0; u < UNROLL; u += 2) {
            acc0 += bce4(P[u], T[u]);
            acc1 += bce4(P[u + 1], T[u + 1]);
        }
    }

    // scalar tail for elements beyond full tiles (none for this shape)
    for (int j = ntiles * TILE_F4 * 4 + blockIdx.x * blockDim.x + threadIdx.x;
         j < n; j += gridDim.x * blockDim.x)
        acc1 += bce_term(pred[j], targ[j]);

    float acc = acc0 + acc1;

    // ---- block reduction (warp shuffle + one smem pass) ----
    __shared__ float s_warp[NWARP];
    const int lane = threadIdx.x & 31;
    const int wid  = threadIdx.x >> 5;

    acc = warp_sum(acc);
    if (lane == 0) s_warp[wid] = acc;
    __syncthreads();

    if (wid == 0) {
        float v = (lane < NWARP) ? s_warp[lane] : 0.0f;
        v = warp_sum(v);
        if (lane == 0) g_partials[blockIdx.x] = v;
    }

    // ---- last-block final reduce (deterministic: fixed-order read) ----
    __shared__ bool s_last;
    if (threadIdx.x == 0) {
        __threadfence();  // make g_partials[blockIdx.x] globally visible
        unsigned int tk = atomicAdd(&g_ticket, 1u);
        s_last = (tk == (unsigned int)(gridDim.x - 1));
    }
    __syncthreads();

    if (s_last) {
        float v = 0.0f;
        for (int k = threadIdx.x; k < NBLK; k += NTHR)
            v += g_partials[k];
        v = warp_sum(v);
        if (lane == 0) s_warp[wid] = v;
        __syncthreads();
        if (wid == 0) {
            float r = (lane < NWARP) ? s_warp[lane] : 0.0f;
            r = warp_sum(r);
            if (lane == 0) {
                out[0] = r;
                g_ticket = 0;   // reset for next (graph-replayed) run
            }
        }
    }
}

extern "C" void kernel_launch(void* const* d_in, const int* in_sizes, int n_in,
                              void* d_out, int out_size) {
    const float* pred = (const float*)d_in[0];
    const float* targ = (const float*)d_in[1];
    const int n = in_sizes[0];
    const int n4 = n >> 2;

    bce_fused_kernel<<<NBLK, NTHR>>>(
        (const float4*)pred, (const float4*)targ, pred, targ, n4, n,
        (float*)d_out);
}